// round 17
// baseline (speedup 1.0000x reference)
#include <cuda_runtime.h>

// NetNew_17162689315115 — R17: TRANSPOSED flat-stream constant weights.
// Per layer, weights stored column-major (wT[k*13+j] = W[j][k]) and streamed
// as LDC.128 with compile-time (j,k) lane routing: consecutive FMAs target 13
// DIFFERENT accumulators (RAW distance 13 >> FMA lat 4) -> serial-chain
// stalls eliminated. Load count and FFMA count both exact (no waste).
// h[80] register-resident, launch_bounds(128,7). Per-j accumulation is still
// ascending-k -> numerics identical to R1.

struct NetParams {
    const float* x;
    float*       out;
    int          B;
};
struct PrepParams {
    const float* W[9];   // W1..W8, Wf
};

template <int L> struct LC {
    static constexpr int DIN  = 8 + 9 * L;
    static constexpr int NTOT = 13 * DIN;
    static constexpr int N4   = (NTOT + 3) & ~3;   // padded block length
    static constexpr int BASE = 72 - 9 * L;        // first input feature index
};
template <int L> struct LOff;
template <> struct LOff<0> { static constexpr int V = 0; };
template <int L> struct LOff {
    static constexpr int V = LOff<L - 1>::V + LC<L - 1>::N4;
};
static constexpr int WF_OFF   = LOff<7>::V + LC<7>::N4;   // 4120
static constexpr int CW_TOTAL = WF_OFF + 80;              // 4200

__constant__ __align__(16) float cw[CW_TOTAL];
__device__   __align__(16) float g_wpad[CW_TOTAL];

__device__ __forceinline__ float clip_mag(float v, float mx) {
    // matches jnp.where(|v| >= mx, v * |mx/v|, v) incl. inf -> NaN edge case
    if (fabsf(v) >= mx) v = v * fabsf(mx / v);
    return v;
}

// ---- prep: per layer, store transposed flat: dst[k*13 + j] = W[j*DIN + k] --
__global__ void netnew_prep(PrepParams pp) {
#define STAGE(L)                                                              \
    {                                                                         \
        constexpr int D  = LC<L>::DIN;                                        \
        constexpr int N  = LC<L>::NTOT;                                       \
        constexpr int N4 = LC<L>::N4;                                         \
        const float* g = pp.W[L];                                             \
        for (int i = threadIdx.x; i < N4; i += blockDim.x) {                  \
            float v = 0.0f;                                                   \
            if (i < N) {                                                      \
                int k = i / 13, j = i - k * 13;                               \
                v = g[j * D + k];                                             \
            }                                                                 \
            g_wpad[LOff<L>::V + i] = v;                                       \
        }                                                                     \
    }
    STAGE(0) STAGE(1) STAGE(2) STAGE(3) STAGE(4) STAGE(5) STAGE(6) STAGE(7)
#undef STAGE
    for (int i = threadIdx.x; i < 80; i += blockDim.x)
        g_wpad[WF_OFF + i] = pp.W[8][i];
}

template <int L>
__device__ __forceinline__ void do_layer(float* __restrict__ h) {
    constexpr int NTOT = LC<L>::NTOT;
    constexpr int N4   = LC<L>::N4;
    constexpr int BASE = LC<L>::BASE;

    float z[13];
#pragma unroll
    for (int j = 0; j < 13; ++j) z[j] = 0.0f;

#pragma unroll
    for (int i4 = 0; i4 < N4; i4 += 4) {
        const float4 w = *reinterpret_cast<const float4*>(cw + LOff<L>::V + i4);
#pragma unroll
        for (int e = 0; e < 4; ++e) {
            const int i = i4 + e;                 // compile-time
            if (i < NTOT) {
                const int k = i / 13;             // compile-time
                const int j = i - k * 13;         // compile-time
                const float wv = (e == 0) ? w.x : (e == 1) ? w.y
                               : (e == 2) ? w.z : w.w;
                z[j] = fmaf(wv, h[BASE + k], z[j]);
            }
        }
    }

    float* o = h + (BASE - 9);
    o[0] = z[0] + z[1];
    o[1] = z[2] - z[3];
    o[2] = clip_mag(z[4] * z[5], 99999999.0f);
    {
        float b   = z[7];
        float den = (b == 0.0f) ? (b + 0.0001f) : b;
        o[3] = clip_mag(z[6] / den, 9999.0f);
    }
    o[4] = sinf(z[8]);
    o[5] = cosf(z[9]);
    {
        float a = z[10];
        if (a >= 17.0f) a = a * (17.0f / a);
        o[6] = expf(a);
    }
    o[7] = logf(fabsf(z[11]));
    o[8] = clip_mag(z[12] * z[12], 99999999.0f);
}

__global__ __launch_bounds__(128, 7)
void netnew_kernel17(NetParams p) {
    const int row = blockIdx.x * blockDim.x + threadIdx.x;
    if (row >= p.B) return;

    // h layout: [outs8 | outs7 | ... | outs1 | x]; x at [72..79].
    float h[80];
    {
        const float4* xr = reinterpret_cast<const float4*>(p.x + (size_t)row * 8);
        float4 a = xr[0], b = xr[1];
        h[72] = a.x; h[73] = a.y; h[74] = a.z; h[75] = a.w;
        h[76] = b.x; h[77] = b.y; h[78] = b.z; h[79] = b.w;
    }

    do_layer<0>(h);
    do_layer<1>(h);
    do_layer<2>(h);
    do_layer<3>(h);
    do_layer<4>(h);
    do_layer<5>(h);
    do_layer<6>(h);
    do_layer<7>(h);

    // final: out = dot(Wf, h[0..79]), sequential ascending k (WF_OFF%4==0)
    float acc = 0.0f;
#pragma unroll
    for (int k = 0; k < 80; k += 4) {
        const float4 w = *reinterpret_cast<const float4*>(cw + WF_OFF + k);
        acc = fmaf(w.x, h[k + 0], acc);
        acc = fmaf(w.y, h[k + 1], acc);
        acc = fmaf(w.z, h[k + 2], acc);
        acc = fmaf(w.w, h[k + 3], acc);
    }
    p.out[row] = acc;
}

extern "C" void kernel_launch(void* const* d_in, const int* in_sizes, int n_in,
                              void* d_out, int out_size) {
    PrepParams pp;
    for (int i = 0; i < 9; ++i) pp.W[i] = (const float*)d_in[1 + i];

    NetParams p;
    p.x   = (const float*)d_in[0];
    p.out = (float*)d_out;
    p.B   = in_sizes[0] / 8;

    // stage transposed flat weight image, then ONE D2D copy into constant
    netnew_prep<<<1, 256>>>(pp);
    void* src = nullptr;
    cudaGetSymbolAddress(&src, g_wpad);
    cudaMemcpyToSymbolAsync(cw, src, CW_TOTAL * sizeof(float), 0,
                            cudaMemcpyDeviceToDevice, 0);

    const int threads = 128;
    const int blocks  = (p.B + threads - 1) / threads;
    netnew_kernel17<<<blocks, threads>>>(p);
}